// round 1
// baseline (speedup 1.0000x reference)
#include <cuda_runtime.h>
#include <math.h>

#define NROWS 50000
#define LDIM  1024
#define NA    512

// ---------------- scratch (device globals; no allocation allowed) ----------
__device__ float g_G[NA * NA];
__device__ float g_H0[NA * NA];
__device__ float g_H1[NA * NA];
__device__ float g_S[NA * NA];
__device__ float g_c[2];              // [0]=c, [1]=1/c
__device__ float g_lam[NROWS + 128];
__device__ float g_y[(size_t)NROWS * NA];
__device__ float g_zb[(size_t)NROWS * NA];

__device__ __forceinline__ float softplus_f(float x) {
    return x > 20.f ? x : log1pf(expf(x));
}
__device__ __forceinline__ float soft_thresh(float v, float l) {
    float a = fabsf(v) - l;
    return a > 0.f ? copysignf(a, v) : 0.f;
}

// ---------------- G = D^T D  (512x512, K=1024) -----------------------------
__global__ void kG(const float* __restrict__ D) {
    __shared__ float Ds1[32][33];
    __shared__ float Ds2[32][33];
    int i0 = blockIdx.x * 32, j0 = blockIdx.y * 32;
    int tid = threadIdx.x;
    int kr = tid >> 3, c4 = (tid & 7) * 4;
    int ty = tid >> 4, tx = tid & 15;
    float acc00 = 0.f, acc01 = 0.f, acc10 = 0.f, acc11 = 0.f;
    for (int k0 = 0; k0 < LDIM; k0 += 32) {
        float4 a = *(const float4*)(D + (size_t)(k0 + kr) * NA + i0 + c4);
        float4 b = *(const float4*)(D + (size_t)(k0 + kr) * NA + j0 + c4);
        Ds1[kr][c4] = a.x; Ds1[kr][c4 + 1] = a.y; Ds1[kr][c4 + 2] = a.z; Ds1[kr][c4 + 3] = a.w;
        Ds2[kr][c4] = b.x; Ds2[kr][c4 + 1] = b.y; Ds2[kr][c4 + 2] = b.z; Ds2[kr][c4 + 3] = b.w;
        __syncthreads();
#pragma unroll
        for (int kk = 0; kk < 32; kk++) {
            float a0 = Ds1[kk][ty * 2], a1 = Ds1[kk][ty * 2 + 1];
            float b0 = Ds2[kk][tx * 2], b1 = Ds2[kk][tx * 2 + 1];
            acc00 = fmaf(a0, b0, acc00); acc01 = fmaf(a0, b1, acc01);
            acc10 = fmaf(a1, b0, acc10); acc11 = fmaf(a1, b1, acc11);
        }
        __syncthreads();
    }
    int i = i0 + ty * 2, j = j0 + tx * 2;
    g_G[i * NA + j] = acc00;       g_G[i * NA + j + 1] = acc01;
    g_G[(i + 1) * NA + j] = acc10; g_G[(i + 1) * NA + j + 1] = acc11;
}

// ---------------- H_out = alpha * H_in * H_in (512^3 square) ---------------
// sel: 0 G->H0, 1 H0->H1, 2 H1->H0
__global__ void kSq(int sel, float alpha) {
    const float* Hin = (sel == 0) ? g_G : (sel == 1) ? g_H0 : g_H1;
    float* Hout = (sel == 1) ? g_H1 : g_H0;
    __shared__ float As[32][33];
    __shared__ float Bs[32][33];
    int i0 = blockIdx.y * 32, j0 = blockIdx.x * 32;
    int tid = threadIdx.x;
    int r = tid >> 3, c4 = (tid & 7) * 4;
    int ty = tid >> 4, tx = tid & 15;
    float acc00 = 0.f, acc01 = 0.f, acc10 = 0.f, acc11 = 0.f;
    for (int k0 = 0; k0 < NA; k0 += 32) {
        float4 a = *(const float4*)(Hin + (size_t)(i0 + r) * NA + k0 + c4);
        As[c4][r] = a.x; As[c4 + 1][r] = a.y; As[c4 + 2][r] = a.z; As[c4 + 3][r] = a.w;
        float4 b = *(const float4*)(Hin + (size_t)(k0 + r) * NA + j0 + c4);
        Bs[r][c4] = b.x; Bs[r][c4 + 1] = b.y; Bs[r][c4 + 2] = b.z; Bs[r][c4 + 3] = b.w;
        __syncthreads();
#pragma unroll
        for (int kk = 0; kk < 32; kk++) {
            float a0 = As[kk][ty * 2], a1 = As[kk][ty * 2 + 1];
            float b0 = Bs[kk][tx * 2], b1 = Bs[kk][tx * 2 + 1];
            acc00 = fmaf(a0, b0, acc00); acc01 = fmaf(a0, b1, acc01);
            acc10 = fmaf(a1, b0, acc10); acc11 = fmaf(a1, b1, acc11);
        }
        __syncthreads();
    }
    int i = i0 + ty * 2, j = j0 + tx * 2;
    Hout[i * NA + j] = alpha * acc00;       Hout[i * NA + j + 1] = alpha * acc01;
    Hout[(i + 1) * NA + j] = alpha * acc10; Hout[(i + 1) * NA + j + 1] = alpha * acc11;
}

// ---------------- power iteration on H1 (= scaled G^64) + Rayleigh on G ----
__global__ void kPow() {
    __shared__ float v[NA];
    __shared__ float red[NA];
    int t = threadIdx.x;  // 512 threads
    v[t] = 1.f;
    __syncthreads();
    for (int it = 0; it < 24; it++) {
        float s = 0.f;
        const float4* row = (const float4*)(g_H1 + (size_t)t * NA);
#pragma unroll 4
        for (int k = 0; k < NA / 4; k++) {
            float4 h = row[k];
            s = fmaf(h.x, v[4 * k], s);
            s = fmaf(h.y, v[4 * k + 1], s);
            s = fmaf(h.z, v[4 * k + 2], s);
            s = fmaf(h.w, v[4 * k + 3], s);
        }
        red[t] = s * s;
        __syncthreads();
        for (int off = 256; off > 0; off >>= 1) {
            if (t < off) red[t] += red[t + off];
            __syncthreads();
        }
        float inv = rsqrtf(red[0]);
        __syncthreads();
        v[t] = s * inv;
        __syncthreads();
    }
    // Rayleigh quotient with original G
    float u = 0.f;
    const float4* grow = (const float4*)(g_G + (size_t)t * NA);
#pragma unroll 4
    for (int k = 0; k < NA / 4; k++) {
        float4 h = grow[k];
        u = fmaf(h.x, v[4 * k], u);
        u = fmaf(h.y, v[4 * k + 1], u);
        u = fmaf(h.z, v[4 * k + 2], u);
        u = fmaf(h.w, v[4 * k + 3], u);
    }
    float vt = v[t];
    red[t] = u * vt;
    __syncthreads();
    for (int off = 256; off > 0; off >>= 1) {
        if (t < off) red[t] += red[t + off];
        __syncthreads();
    }
    float num = red[0];
    __syncthreads();
    red[t] = vt * vt;
    __syncthreads();
    for (int off = 256; off > 0; off >>= 1) {
        if (t < off) red[t] += red[t + off];
        __syncthreads();
    }
    if (t == 0) {
        float c = num / red[0];
        g_c[0] = c;
        g_c[1] = 1.f / c;
    }
}

// ---------------- S = I - G/c ----------------------------------------------
__global__ void kS() {
    int idx = blockIdx.x * 256 + threadIdx.x;
    float ic = g_c[1];
    int i = idx >> 9, j = idx & (NA - 1);
    float val = -g_G[idx] * ic;
    if (i == j) val += 1.f;
    g_S[idx] = val;
}

// ---------------- fused MLP -> lam ------------------------------------------
// block: 128 rows, 256 threads. dynamic smem:
//   hbuf[128][132]  (67584 B)  then region1 = max(As+Bs 16KB, ws2+h2buf 69632 B)
extern __shared__ float smem_mlp[];
__global__ void kMLP(const float* __restrict__ x,
                     const float* __restrict__ w1, const float* __restrict__ b1,
                     const float* __restrict__ gg1, const float* __restrict__ be1,
                     const float* __restrict__ w2, const float* __restrict__ b2,
                     const float* __restrict__ gg2, const float* __restrict__ be2,
                     const float* __restrict__ w3, const float* __restrict__ b3) {
    const int LDH = 132;
    int m0 = blockIdx.x * 128;
    int tid = threadIdx.x;
    float* hbuf = smem_mlp;
    float* r1 = smem_mlp + 128 * LDH;
    float* As = r1;            // [16][128]
    float* Bs = r1 + 16 * 128; // [16][128]
    int ty = tid >> 4, tx = tid & 15;
    float acc[8][8];
#pragma unroll
    for (int i = 0; i < 8; i++)
#pragma unroll
        for (int j = 0; j < 8; j++) acc[i][j] = 0.f;

    for (int k0 = 0; k0 < LDIM; k0 += 16) {
#pragma unroll
        for (int i = 0; i < 2; i++) {
            int idx = tid * 2 + i;
            int row = idx >> 2, kq = (idx & 3) * 4;
            float4 a = make_float4(0.f, 0.f, 0.f, 0.f);
            if (m0 + row < NROWS) a = *(const float4*)(x + (size_t)(m0 + row) * LDIM + k0 + kq);
            As[(kq + 0) * 128 + row] = a.x;
            As[(kq + 1) * 128 + row] = a.y;
            As[(kq + 2) * 128 + row] = a.z;
            As[(kq + 3) * 128 + row] = a.w;
        }
#pragma unroll
        for (int i = 0; i < 2; i++) {
            int idx = tid * 2 + i;
            int br = idx >> 5, bc = (idx & 31) * 4;
            *(float4*)(Bs + br * 128 + bc) = *(const float4*)(w1 + (size_t)(k0 + br) * 128 + bc);
        }
        __syncthreads();
#pragma unroll
        for (int kk = 0; kk < 16; kk++) {
            float4 a0 = *(float4*)(As + kk * 128 + ty * 8);
            float4 a1 = *(float4*)(As + kk * 128 + ty * 8 + 4);
            float4 b0 = *(float4*)(Bs + kk * 128 + tx * 8);
            float4 b1 = *(float4*)(Bs + kk * 128 + tx * 8 + 4);
            float av[8] = {a0.x, a0.y, a0.z, a0.w, a1.x, a1.y, a1.z, a1.w};
            float bv[8] = {b0.x, b0.y, b0.z, b0.w, b1.x, b1.y, b1.z, b1.w};
#pragma unroll
            for (int i = 0; i < 8; i++)
#pragma unroll
                for (int j = 0; j < 8; j++) acc[i][j] = fmaf(av[i], bv[j], acc[i][j]);
        }
        __syncthreads();
    }
#pragma unroll
    for (int i = 0; i < 8; i++) {
        int r = ty * 8 + i;
#pragma unroll
        for (int j = 0; j < 8; j++) {
            int c = tx * 8 + j;
            hbuf[r * LDH + c] = acc[i][j] + b1[c];
        }
    }
    __syncthreads();
    // LN1 + softplus over 128 per row
    int warp = tid >> 5, lane = tid & 31;
    for (int r = warp; r < 128; r += 8) {
        float vals[4];
        float s = 0.f, s2 = 0.f;
#pragma unroll
        for (int i = 0; i < 4; i++) {
            float h = hbuf[r * LDH + lane * 4 + i];
            vals[i] = h; s += h; s2 += h * h;
        }
#pragma unroll
        for (int off = 16; off; off >>= 1) {
            s += __shfl_xor_sync(0xffffffffu, s, off);
            s2 += __shfl_xor_sync(0xffffffffu, s2, off);
        }
        float mu = s * (1.f / 128.f);
        float var = s2 * (1.f / 128.f) - mu * mu;
        float inv = rsqrtf(var + 1e-5f);
#pragma unroll
        for (int i = 0; i < 4; i++) {
            int c = lane * 4 + i;
            float t2 = (vals[i] - mu) * inv * gg1[c] + be1[c];
            hbuf[r * LDH + c] = softplus_f(t2);
        }
    }
    __syncthreads();
    // Phase C: h2 = hbuf @ w2 + b2
    float* ws2 = r1;             // [128][64]
    float* h2 = r1 + 128 * 64;   // [128][72]
    const int LDH2 = 72;
#pragma unroll
    for (int i = 0; i < 8; i++) {
        int idx = i * 256 + tid;
        *(float4*)(ws2 + idx * 4) = *(const float4*)(w2 + (size_t)idx * 4);
    }
    __syncthreads();
    {
        int r0 = (tid >> 3) * 4, c0 = (tid & 7) * 8;
        float a2[4][8];
#pragma unroll
        for (int i = 0; i < 4; i++)
#pragma unroll
            for (int j = 0; j < 8; j++) a2[i][j] = 0.f;
        for (int k = 0; k < 128; k++) {
            float av[4], bv[8];
#pragma unroll
            for (int i = 0; i < 4; i++) av[i] = hbuf[(r0 + i) * LDH + k];
#pragma unroll
            for (int j = 0; j < 8; j++) bv[j] = ws2[k * 64 + c0 + j];
#pragma unroll
            for (int i = 0; i < 4; i++)
#pragma unroll
                for (int j = 0; j < 8; j++) a2[i][j] = fmaf(av[i], bv[j], a2[i][j]);
        }
#pragma unroll
        for (int i = 0; i < 4; i++)
#pragma unroll
            for (int j = 0; j < 8; j++)
                h2[(r0 + i) * LDH2 + c0 + j] = a2[i][j] + b2[c0 + j];
    }
    __syncthreads();
    // LN2 + softplus over 64
    for (int r = warp; r < 128; r += 8) {
        float vals[2];
        float s = 0.f, s2 = 0.f;
#pragma unroll
        for (int i = 0; i < 2; i++) {
            float h = h2[r * LDH2 + lane * 2 + i];
            vals[i] = h; s += h; s2 += h * h;
        }
#pragma unroll
        for (int off = 16; off; off >>= 1) {
            s += __shfl_xor_sync(0xffffffffu, s, off);
            s2 += __shfl_xor_sync(0xffffffffu, s2, off);
        }
        float mu = s * (1.f / 64.f);
        float var = s2 * (1.f / 64.f) - mu * mu;
        float inv = rsqrtf(var + 1e-5f);
#pragma unroll
        for (int i = 0; i < 2; i++) {
            int c = lane * 2 + i;
            float t2 = (vals[i] - mu) * inv * gg2[c] + be2[c];
            h2[r * LDH2 + c] = softplus_f(t2);
        }
    }
    __syncthreads();
    // lam
    if (tid < 128) {
        int r = tid;
        float s = 0.f;
        for (int k = 0; k < 64; k++) s = fmaf(h2[r * LDH2 + k], w3[k], s);
        if (m0 + r < NROWS) g_lam[m0 + r] = s + b3[0];
    }
}

// ---------------- big GEMMs: 128x128 tile, 256 thr, 8x8/thread -------------
// FIRST=true : out y = A@B (A=x, B=Dict, K=1024); also z0 = st(y) -> g_zb
// FIRST=false: z_out = st(A@S + y/c)   (A,zout selected by dir)
template <int K, int LDA, bool FIRST>
__global__ void kBig(const float* __restrict__ Aext, float* __restrict__ Zext, int dir) {
    __shared__ float As[16 * 128];
    __shared__ float Bs[16 * 128];
    const float* A;
    const float* B;
    float* zout;
    if (FIRST) {
        A = Aext;            // x
        B = Zext;            // Dict (passed via Zext slot, const-cast below ok)
        zout = g_zb;
    } else {
        A = dir ? Aext : g_zb;
        B = g_S;
        zout = dir ? g_zb : Zext;
    }
    int m0 = blockIdx.y * 128, n0 = blockIdx.x * 128;
    int tid = threadIdx.x, ty = tid >> 4, tx = tid & 15;
    float acc[8][8];
#pragma unroll
    for (int i = 0; i < 8; i++)
#pragma unroll
        for (int j = 0; j < 8; j++) acc[i][j] = 0.f;

    for (int k0 = 0; k0 < K; k0 += 16) {
#pragma unroll
        for (int i = 0; i < 2; i++) {
            int idx = tid * 2 + i;
            int row = idx >> 2, kq = (idx & 3) * 4;
            float4 a = make_float4(0.f, 0.f, 0.f, 0.f);
            if (m0 + row < NROWS) a = *(const float4*)(A + (size_t)(m0 + row) * LDA + k0 + kq);
            As[(kq + 0) * 128 + row] = a.x;
            As[(kq + 1) * 128 + row] = a.y;
            As[(kq + 2) * 128 + row] = a.z;
            As[(kq + 3) * 128 + row] = a.w;
        }
#pragma unroll
        for (int i = 0; i < 2; i++) {
            int idx = tid * 2 + i;
            int br = idx >> 5, bc = (idx & 31) * 4;
            *(float4*)(Bs + br * 128 + bc) = *(const float4*)(B + (size_t)(k0 + br) * NA + n0 + bc);
        }
        __syncthreads();
#pragma unroll
        for (int kk = 0; kk < 16; kk++) {
            float4 a0 = *(float4*)(As + kk * 128 + ty * 8);
            float4 a1 = *(float4*)(As + kk * 128 + ty * 8 + 4);
            float4 b0 = *(float4*)(Bs + kk * 128 + tx * 8);
            float4 b1 = *(float4*)(Bs + kk * 128 + tx * 8 + 4);
            float av[8] = {a0.x, a0.y, a0.z, a0.w, a1.x, a1.y, a1.z, a1.w};
            float bv[8] = {b0.x, b0.y, b0.z, b0.w, b1.x, b1.y, b1.z, b1.w};
#pragma unroll
            for (int i = 0; i < 8; i++)
#pragma unroll
                for (int j = 0; j < 8; j++) acc[i][j] = fmaf(av[i], bv[j], acc[i][j]);
        }
        __syncthreads();
    }
    float ic = g_c[1];
#pragma unroll
    for (int i = 0; i < 8; i++) {
        int r = m0 + ty * 8 + i;
        if (r >= NROWS) break;
        float l = g_lam[r] * ic;
        int base = r * NA + n0 + tx * 8;
#pragma unroll
        for (int j = 0; j < 8; j++) {
            float v = acc[i][j];
            if (FIRST) {
                g_y[base + j] = v;
            } else {
                v = fmaf(g_y[base + j], ic, v);
            }
            zout[base + j] = soft_thresh(v, l);
        }
    }
}

// ---------------- launch ----------------------------------------------------
extern "C" void kernel_launch(void* const* d_in, const int* in_sizes, int n_in,
                              void* d_out, int out_size) {
    const float* x    = (const float*)d_in[0];
    const float* Dict = (const float*)d_in[1];
    const float* w1   = (const float*)d_in[2];
    const float* b1   = (const float*)d_in[3];
    const float* gg1  = (const float*)d_in[4];
    const float* be1  = (const float*)d_in[5];
    const float* w2   = (const float*)d_in[6];
    const float* b2   = (const float*)d_in[7];
    const float* gg2  = (const float*)d_in[8];
    const float* be2  = (const float*)d_in[9];
    const float* w3   = (const float*)d_in[10];
    const float* b3   = (const float*)d_in[11];
    float* out = (float*)d_out;

    // c = ||Dict||_2^2 via G = D^T D, 6 squarings (G^64), power iters, Rayleigh
    kG<<<dim3(16, 16), 256>>>(Dict);
    kSq<<<dim3(16, 16), 256>>>(0, 1.f);                  // G^2  -> H0
    kSq<<<dim3(16, 16), 256>>>(1, 1.f);                  // G^4  -> H1
    kSq<<<dim3(16, 16), 256>>>(2, 1.f);                  // G^8  -> H0
    kSq<<<dim3(16, 16), 256>>>(1, 1.f);                  // G^16 -> H1
    kSq<<<dim3(16, 16), 256>>>(2, 1.f);                  // G^32 -> H0
    kSq<<<dim3(16, 16), 256>>>(1, 7.8886090522e-31f);    // 2^-100 * G^64 -> H1
    kPow<<<1, 512>>>();
    kS<<<(NA * NA) / 256, 256>>>();

    // MLP -> lam
    static bool attr_set = false;
    size_t mlp_smem = (size_t)128 * 132 * 4 + (size_t)(128 * 64 + 128 * 72) * 4;
    cudaFuncSetAttribute(kMLP, cudaFuncAttributeMaxDynamicSharedMemorySize, (int)mlp_smem);
    (void)attr_set;
    int rb = (NROWS + 127) / 128;
    kMLP<<<rb, 256, mlp_smem>>>(x, w1, b1, gg1, be1, w2, b2, gg2, be2, w3, b3);

    // y = x @ Dict, z0 = st(y) -> g_zb
    kBig<LDIM, LDIM, true><<<dim3(4, rb), 256>>>(x, (float*)Dict, 0);

    // 5 iterations, ping-pong g_zb <-> d_out, ending in d_out
    kBig<NA, NA, false><<<dim3(4, rb), 256>>>(out, out, 0); // zb   -> out
    kBig<NA, NA, false><<<dim3(4, rb), 256>>>(out, out, 1); // out  -> zb
    kBig<NA, NA, false><<<dim3(4, rb), 256>>>(out, out, 0); // zb   -> out
    kBig<NA, NA, false><<<dim3(4, rb), 256>>>(out, out, 1); // out  -> zb
    kBig<NA, NA, false><<<dim3(4, rb), 256>>>(out, out, 0); // zb   -> out
}

// round 3
// speedup vs baseline: 1.7450x; 1.7450x over previous
#include <cuda_runtime.h>
#include <cuda_bf16.h>
#include <math.h>
#include <stdint.h>

#define NROWS 50000
#define LDIM  1024
#define NA    512

// ---------------- scratch (device globals; no allocation allowed) ----------
__device__ float g_G[NA * NA];
__device__ float g_H0[NA * NA];
__device__ float g_H1[NA * NA];
__device__ float g_c[2];              // [0]=c, [1]=1/c
__device__ float g_lam[NROWS + 128];
__device__ float g_y[(size_t)NROWS * NA];
__device__ __nv_bfloat16 g_Sh[NA * NA];
__device__ __nv_bfloat16 g_Sl[NA * NA];
__device__ __nv_bfloat16 g_Dth[NA * LDIM];
__device__ __nv_bfloat16 g_Dtl[NA * LDIM];
__device__ __nv_bfloat16 g_xh[(size_t)NROWS * LDIM];
__device__ __nv_bfloat16 g_xl[(size_t)NROWS * LDIM];
__device__ __nv_bfloat16 g_zah[(size_t)NROWS * NA];
__device__ __nv_bfloat16 g_zal[(size_t)NROWS * NA];
__device__ __nv_bfloat16 g_zbh[(size_t)NROWS * NA];
__device__ __nv_bfloat16 g_zbl[(size_t)NROWS * NA];

__device__ __forceinline__ float softplus_f(float x) {
    return x > 20.f ? x : log1pf(expf(x));
}
__device__ __forceinline__ float soft_thresh(float v, float l) {
    float a = fabsf(v) - l;
    return a > 0.f ? copysignf(a, v) : 0.f;
}
__device__ __forceinline__ uint32_t pack_bf16(float a, float b) {
    __nv_bfloat162 h = __floats2bfloat162_rn(a, b);
    return *(uint32_t*)&h;
}
__device__ __forceinline__ uint32_t smem_to_u32(const void* smem_ptr) {
    uint32_t addr;
    asm("{ .reg .u64 tmp; cvta.to.shared.u64 tmp, %1; cvt.u32.u64 %0, tmp; }"
        : "=r"(addr) : "l"(smem_ptr));
    return addr;
}
__device__ __forceinline__ void cp16(uint32_t dst, const void* src) {
    asm volatile("cp.async.cg.shared.global [%0], [%1], 16;\n" :: "r"(dst), "l"(src) : "memory");
}
__device__ __forceinline__ void cp_commit() {
    asm volatile("cp.async.commit_group;\n" ::: "memory");
}
__device__ __forceinline__ void cp_wait1() {
    asm volatile("cp.async.wait_group 1;\n" ::: "memory");
}
__device__ __forceinline__ void ldsm4(uint32_t* r, uint32_t addr) {
    asm volatile("ldmatrix.sync.aligned.m8n8.x4.shared.b16 {%0,%1,%2,%3}, [%4];\n"
                 : "=r"(r[0]), "=r"(r[1]), "=r"(r[2]), "=r"(r[3]) : "r"(addr));
}
__device__ __forceinline__ void mma16816(float* d, const uint32_t* a, const uint32_t* b) {
    asm volatile(
        "mma.sync.aligned.m16n8k16.row.col.f32.bf16.bf16.f32 "
        "{%0,%1,%2,%3}, {%4,%5,%6,%7}, {%8,%9}, {%0,%1,%2,%3};\n"
        : "+f"(d[0]), "+f"(d[1]), "+f"(d[2]), "+f"(d[3])
        : "r"(a[0]), "r"(a[1]), "r"(a[2]), "r"(a[3]), "r"(b[0]), "r"(b[1]));
}

// ---------------- G = D^T D  (512x512, K=1024) -----------------------------
__global__ void kG(const float* __restrict__ D) {
    __shared__ float Ds1[32][33];
    __shared__ float Ds2[32][33];
    int i0 = blockIdx.x * 32, j0 = blockIdx.y * 32;
    int tid = threadIdx.x;
    int kr = tid >> 3, c4 = (tid & 7) * 4;
    int ty = tid >> 4, tx = tid & 15;
    float acc00 = 0.f, acc01 = 0.f, acc10 = 0.f, acc11 = 0.f;
    for (int k0 = 0; k0 < LDIM; k0 += 32) {
        float4 a = *(const float4*)(D + (size_t)(k0 + kr) * NA + i0 + c4);
        float4 b = *(const float4*)(D + (size_t)(k0 + kr) * NA + j0 + c4);
        Ds1[kr][c4] = a.x; Ds1[kr][c4 + 1] = a.y; Ds1[kr][c4 + 2] = a.z; Ds1[kr][c4 + 3] = a.w;
        Ds2[kr][c4] = b.x; Ds2[kr][c4 + 1] = b.y; Ds2[kr][c4 + 2] = b.z; Ds2[kr][c4 + 3] = b.w;
        __syncthreads();
#pragma unroll
        for (int kk = 0; kk < 32; kk++) {
            float a0 = Ds1[kk][ty * 2], a1 = Ds1[kk][ty * 2 + 1];
            float b0 = Ds2[kk][tx * 2], b1 = Ds2[kk][tx * 2 + 1];
            acc00 = fmaf(a0, b0, acc00); acc01 = fmaf(a0, b1, acc01);
            acc10 = fmaf(a1, b0, acc10); acc11 = fmaf(a1, b1, acc11);
        }
        __syncthreads();
    }
    int i = i0 + ty * 2, j = j0 + tx * 2;
    g_G[i * NA + j] = acc00;       g_G[i * NA + j + 1] = acc01;
    g_G[(i + 1) * NA + j] = acc10; g_G[(i + 1) * NA + j + 1] = acc11;
}

// ---------------- H_out = alpha * H_in * H_in (512^3 square) ---------------
__global__ void kSq(int sel, float alpha) {
    const float* Hin = (sel == 0) ? g_G : (sel == 1) ? g_H0 : g_H1;
    float* Hout = (sel == 1) ? g_H1 : g_H0;
    __shared__ float As[32][33];
    __shared__ float Bs[32][33];
    int i0 = blockIdx.y * 32, j0 = blockIdx.x * 32;
    int tid = threadIdx.x;
    int r = tid >> 3, c4 = (tid & 7) * 4;
    int ty = tid >> 4, tx = tid & 15;
    float acc00 = 0.f, acc01 = 0.f, acc10 = 0.f, acc11 = 0.f;
    for (int k0 = 0; k0 < NA; k0 += 32) {
        float4 a = *(const float4*)(Hin + (size_t)(i0 + r) * NA + k0 + c4);
        As[c4][r] = a.x; As[c4 + 1][r] = a.y; As[c4 + 2][r] = a.z; As[c4 + 3][r] = a.w;
        float4 b = *(const float4*)(Hin + (size_t)(k0 + r) * NA + j0 + c4);
        Bs[r][c4] = b.x; Bs[r][c4 + 1] = b.y; Bs[r][c4 + 2] = b.z; Bs[r][c4 + 3] = b.w;
        __syncthreads();
#pragma unroll
        for (int kk = 0; kk < 32; kk++) {
            float a0 = As[kk][ty * 2], a1 = As[kk][ty * 2 + 1];
            float b0 = Bs[kk][tx * 2], b1 = Bs[kk][tx * 2 + 1];
            acc00 = fmaf(a0, b0, acc00); acc01 = fmaf(a0, b1, acc01);
            acc10 = fmaf(a1, b0, acc10); acc11 = fmaf(a1, b1, acc11);
        }
        __syncthreads();
    }
    int i = i0 + ty * 2, j = j0 + tx * 2;
    Hout[i * NA + j] = alpha * acc00;       Hout[i * NA + j + 1] = alpha * acc01;
    Hout[(i + 1) * NA + j] = alpha * acc10; Hout[(i + 1) * NA + j + 1] = alpha * acc11;
}

// ---------------- power iteration on H1 (= scaled G^64) + Rayleigh on G ----
__global__ void kPow() {
    __shared__ float v[NA];
    __shared__ float red[NA];
    int t = threadIdx.x;  // 512 threads
    v[t] = 1.f;
    __syncthreads();
    for (int it = 0; it < 24; it++) {
        float s = 0.f;
        const float4* row = (const float4*)(g_H1 + (size_t)t * NA);
#pragma unroll 4
        for (int k = 0; k < NA / 4; k++) {
            float4 h = row[k];
            s = fmaf(h.x, v[4 * k], s);
            s = fmaf(h.y, v[4 * k + 1], s);
            s = fmaf(h.z, v[4 * k + 2], s);
            s = fmaf(h.w, v[4 * k + 3], s);
        }
        red[t] = s * s;
        __syncthreads();
        for (int off = 256; off > 0; off >>= 1) {
            if (t < off) red[t] += red[t + off];
            __syncthreads();
        }
        float inv = rsqrtf(red[0]);
        __syncthreads();
        v[t] = s * inv;
        __syncthreads();
    }
    float u = 0.f;
    const float4* grow = (const float4*)(g_G + (size_t)t * NA);
#pragma unroll 4
    for (int k = 0; k < NA / 4; k++) {
        float4 h = grow[k];
        u = fmaf(h.x, v[4 * k], u);
        u = fmaf(h.y, v[4 * k + 1], u);
        u = fmaf(h.z, v[4 * k + 2], u);
        u = fmaf(h.w, v[4 * k + 3], u);
    }
    float vt = v[t];
    red[t] = u * vt;
    __syncthreads();
    for (int off = 256; off > 0; off >>= 1) {
        if (t < off) red[t] += red[t + off];
        __syncthreads();
    }
    float num = red[0];
    __syncthreads();
    red[t] = vt * vt;
    __syncthreads();
    for (int off = 256; off > 0; off >>= 1) {
        if (t < off) red[t] += red[t + off];
        __syncthreads();
    }
    if (t == 0) {
        float c = num / red[0];
        g_c[0] = c;
        g_c[1] = 1.f / c;
    }
}

// ---------------- Sh/Sl = split_bf16(I - G/c)  (S symmetric) ---------------
__global__ void kS2() {
    int idx = blockIdx.x * 256 + threadIdx.x;
    float ic = g_c[1];
    int i = idx >> 9, j = idx & (NA - 1);
    float val = -g_G[idx] * ic;
    if (i == j) val += 1.f;
    __nv_bfloat16 h = __float2bfloat16(val);
    g_Sh[idx] = h;
    g_Sl[idx] = __float2bfloat16(val - __bfloat162float(h));
}

// ---------------- x -> xh/xl bf16 split --------------------------------------
__global__ void kCvtX(const float* __restrict__ x) {
    const int NV = NROWS * LDIM / 4;
    uint32_t* xh = (uint32_t*)g_xh;
    uint32_t* xl = (uint32_t*)g_xl;
    for (int v = blockIdx.x * blockDim.x + threadIdx.x; v < NV; v += gridDim.x * blockDim.x) {
        float4 a = *(const float4*)(x + (size_t)v * 4);
        __nv_bfloat16 h0 = __float2bfloat16(a.x), h1 = __float2bfloat16(a.y);
        __nv_bfloat16 h2 = __float2bfloat16(a.z), h3 = __float2bfloat16(a.w);
        float l0 = a.x - __bfloat162float(h0), l1 = a.y - __bfloat162float(h1);
        float l2 = a.z - __bfloat162float(h2), l3 = a.w - __bfloat162float(h3);
        __nv_bfloat162 hh0 = make_bfloat162(h0, h1);
        __nv_bfloat162 hh1 = make_bfloat162(h2, h3);
        xh[v * 2] = *(uint32_t*)&hh0;
        xh[v * 2 + 1] = *(uint32_t*)&hh1;
        xl[v * 2] = pack_bf16(l0, l1);
        xl[v * 2 + 1] = pack_bf16(l2, l3);
    }
}

// ---------------- Dict transpose + split: Dt[n][k] = D[k][n] -----------------
__global__ void kTrD(const float* __restrict__ D) {
    __shared__ float t[32][33];
    int k0 = blockIdx.x * 32, n0 = blockIdx.y * 32;
    int tx = threadIdx.x & 31, ty = threadIdx.x >> 5;  // 256 threads, ty 0..7
    for (int i = ty; i < 32; i += 8) t[i][tx] = D[(size_t)(k0 + i) * NA + n0 + tx];
    __syncthreads();
    for (int i = ty; i < 32; i += 8) {
        float val = t[tx][i];
        size_t o = (size_t)(n0 + i) * LDIM + k0 + tx;
        __nv_bfloat16 h = __float2bfloat16(val);
        g_Dth[o] = h;
        g_Dtl[o] = __float2bfloat16(val - __bfloat162float(h));
    }
}

// ---------------- fused MLP -> lam ------------------------------------------
extern __shared__ float smem_mlp[];
__global__ void kMLP(const float* __restrict__ x,
                     const float* __restrict__ w1, const float* __restrict__ b1,
                     const float* __restrict__ gg1, const float* __restrict__ be1,
                     const float* __restrict__ w2, const float* __restrict__ b2,
                     const float* __restrict__ gg2, const float* __restrict__ be2,
                     const float* __restrict__ w3, const float* __restrict__ b3) {
    const int LDH = 132;
    int m0 = blockIdx.x * 128;
    int tid = threadIdx.x;
    float* hbuf = smem_mlp;
    float* r1 = smem_mlp + 128 * LDH;
    float* As = r1;            // [16][128]
    float* Bs = r1 + 16 * 128; // [16][128]
    int ty = tid >> 4, tx = tid & 15;
    float acc[8][8];
#pragma unroll
    for (int i = 0; i < 8; i++)
#pragma unroll
        for (int j = 0; j < 8; j++) acc[i][j] = 0.f;

    for (int k0 = 0; k0 < LDIM; k0 += 16) {
#pragma unroll
        for (int i = 0; i < 2; i++) {
            int idx = tid * 2 + i;
            int row = idx >> 2, kq = (idx & 3) * 4;
            float4 a = make_float4(0.f, 0.f, 0.f, 0.f);
            if (m0 + row < NROWS) a = *(const float4*)(x + (size_t)(m0 + row) * LDIM + k0 + kq);
            As[(kq + 0) * 128 + row] = a.x;
            As[(kq + 1) * 128 + row] = a.y;
            As[(kq + 2) * 128 + row] = a.z;
            As[(kq + 3) * 128 + row] = a.w;
        }
#pragma unroll
        for (int i = 0; i < 2; i++) {
            int idx = tid * 2 + i;
            int br = idx >> 5, bc = (idx & 31) * 4;
            *(float4*)(Bs + br * 128 + bc) = *(const float4*)(w1 + (size_t)(k0 + br) * 128 + bc);
        }
        __syncthreads();
#pragma unroll
        for (int kk = 0; kk < 16; kk++) {
            float4 a0 = *(float4*)(As + kk * 128 + ty * 8);
            float4 a1 = *(float4*)(As + kk * 128 + ty * 8 + 4);
            float4 b0 = *(float4*)(Bs + kk * 128 + tx * 8);
            float4 b1 = *(float4*)(Bs + kk * 128 + tx * 8 + 4);
            float av[8] = {a0.x, a0.y, a0.z, a0.w, a1.x, a1.y, a1.z, a1.w};
            float bv[8] = {b0.x, b0.y, b0.z, b0.w, b1.x, b1.y, b1.z, b1.w};
#pragma unroll
            for (int i = 0; i < 8; i++)
#pragma unroll
                for (int j = 0; j < 8; j++) acc[i][j] = fmaf(av[i], bv[j], acc[i][j]);
        }
        __syncthreads();
    }
#pragma unroll
    for (int i = 0; i < 8; i++) {
        int r = ty * 8 + i;
#pragma unroll
        for (int j = 0; j < 8; j++) {
            int c = tx * 8 + j;
            hbuf[r * LDH + c] = acc[i][j] + b1[c];
        }
    }
    __syncthreads();
    int warp = tid >> 5, lane = tid & 31;
    for (int r = warp; r < 128; r += 8) {
        float vals[4];
        float s = 0.f, s2 = 0.f;
#pragma unroll
        for (int i = 0; i < 4; i++) {
            float h = hbuf[r * LDH + lane * 4 + i];
            vals[i] = h; s += h; s2 += h * h;
        }
#pragma unroll
        for (int off = 16; off; off >>= 1) {
            s += __shfl_xor_sync(0xffffffffu, s, off);
            s2 += __shfl_xor_sync(0xffffffffu, s2, off);
        }
        float mu = s * (1.f / 128.f);
        float var = s2 * (1.f / 128.f) - mu * mu;
        float inv = rsqrtf(var + 1e-5f);
#pragma unroll
        for (int i = 0; i < 4; i++) {
            int c = lane * 4 + i;
            float t2 = (vals[i] - mu) * inv * gg1[c] + be1[c];
            hbuf[r * LDH + c] = softplus_f(t2);
        }
    }
    __syncthreads();
    float* ws2 = r1;             // [128][64]
    float* h2 = r1 + 128 * 64;   // [128][72]
    const int LDH2 = 72;
#pragma unroll
    for (int i = 0; i < 8; i++) {
        int idx = i * 256 + tid;
        *(float4*)(ws2 + idx * 4) = *(const float4*)(w2 + (size_t)idx * 4);
    }
    __syncthreads();
    {
        int r0 = (tid >> 3) * 4, c0 = (tid & 7) * 8;
        float a2[4][8];
#pragma unroll
        for (int i = 0; i < 4; i++)
#pragma unroll
            for (int j = 0; j < 8; j++) a2[i][j] = 0.f;
        for (int k = 0; k < 128; k++) {
            float av[4], bv[8];
#pragma unroll
            for (int i = 0; i < 4; i++) av[i] = hbuf[(r0 + i) * LDH + k];
#pragma unroll
            for (int j = 0; j < 8; j++) bv[j] = ws2[k * 64 + c0 + j];
#pragma unroll
            for (int i = 0; i < 4; i++)
#pragma unroll
                for (int j = 0; j < 8; j++) a2[i][j] = fmaf(av[i], bv[j], a2[i][j]);
        }
#pragma unroll
        for (int i = 0; i < 4; i++)
#pragma unroll
            for (int j = 0; j < 8; j++)
                h2[(r0 + i) * LDH2 + c0 + j] = a2[i][j] + b2[c0 + j];
    }
    __syncthreads();
    for (int r = warp; r < 128; r += 8) {
        float vals[2];
        float s = 0.f, s2 = 0.f;
#pragma unroll
        for (int i = 0; i < 2; i++) {
            float h = h2[r * LDH2 + lane * 2 + i];
            vals[i] = h; s += h; s2 += h * h;
        }
#pragma unroll
        for (int off = 16; off; off >>= 1) {
            s += __shfl_xor_sync(0xffffffffu, s, off);
            s2 += __shfl_xor_sync(0xffffffffu, s2, off);
        }
        float mu = s * (1.f / 64.f);
        float var = s2 * (1.f / 64.f) - mu * mu;
        float inv = rsqrtf(var + 1e-5f);
#pragma unroll
        for (int i = 0; i < 2; i++) {
            int c = lane * 2 + i;
            float t2 = (vals[i] - mu) * inv * gg2[c] + be2[c];
            h2[r * LDH2 + c] = softplus_f(t2);
        }
    }
    __syncthreads();
    if (tid < 128) {
        int r = tid;
        float s = 0.f;
        for (int k = 0; k < 64; k++) s = fmaf(h2[r * LDH2 + k], w3[k], s);
        if (m0 + r < NROWS) g_lam[m0 + r] = s + b3[0];
    }
}

// ================= mma.sync split-bf16 GEMM =================================
// CTA 128(M)x128(N), 8 warps (4M x 2N), warp tile 32x64.
// K staged at 64 bf16 (=128B rows), SW128 XOR swizzle, 3-stage cp.async.
// Stage layout (64KB): Ah 0 | Al 16K | Bh 32K | Bl 48K.
// Products per k16: (Ah,Bh), (Ah,Bl), (Al,Bh).
// MODE 0: y = x@Dict (KT=1024), write y fp32 + z0 split
// MODE 1: z' = st(z@S + y/c) (KT=512), write z' split
// MODE 2: same but write fp32 to Fout

#define STAGE_BYTES 65536
#define NSTAGE 3

__device__ __forceinline__ uint32_t sw_off(int row, int c) {
    return (uint32_t)(((row >> 3) << 10) | ((row & 7) << 7) | ((c ^ (row & 7)) << 4));
}

__device__ __forceinline__ void load_stage(uint32_t smbase,
                                           const __nv_bfloat16* Ah, const __nv_bfloat16* Al,
                                           const __nv_bfloat16* Bh, const __nv_bfloat16* Bl,
                                           int m0, int mval, int n0, int k0,
                                           int strideA, int tid) {
#pragma unroll
    for (int t = 0; t < 4; t++) {
        int idx = tid + t * 256;       // 0..1023
        int row = idx >> 3, c = idx & 7;
        uint32_t so = sw_off(row, c);
        int ar = m0 + (row < mval ? row : mval - 1);
        cp16(smbase + so,                 Ah + (size_t)ar * strideA + k0 + c * 8);
        cp16(smbase + 16384 + so,         Al + (size_t)ar * strideA + k0 + c * 8);
        int br = n0 + row;
        cp16(smbase + 32768 + so,         Bh + (size_t)br * strideA + k0 + c * 8);
        cp16(smbase + 49152 + so,         Bl + (size_t)br * strideA + k0 + c * 8);
    }
    cp_commit();
}

extern __shared__ char smem_tc[];

template <int KT, int MODE>
__global__ void __launch_bounds__(256, 1) kTC(int dir, float* __restrict__ Fout) {
    const int NS = KT / 64;
    int tid = threadIdx.x;
    int wid = tid >> 5, lane = tid & 31;
    int wm = wid & 3, wn = wid >> 2;
    int m0 = blockIdx.y * 128;
    int n0 = blockIdx.x * 128;
    int mval = NROWS - m0; if (mval > 128) mval = 128;

    const __nv_bfloat16 *Ah_g, *Al_g, *Bh_g, *Bl_g;
    __nv_bfloat16 *Zh = nullptr, *Zl = nullptr;
    int strideA;
    if (MODE == 0) {
        Ah_g = g_xh; Al_g = g_xl; Bh_g = g_Dth; Bl_g = g_Dtl;
        Zh = g_zah; Zl = g_zal; strideA = LDIM;
    } else {
        Ah_g = dir ? g_zbh : g_zah; Al_g = dir ? g_zbl : g_zal;
        Bh_g = g_Sh; Bl_g = g_Sl;
        Zh = dir ? g_zah : g_zbh;  Zl = dir ? g_zal : g_zbl;
        strideA = NA;
    }

    uint32_t sb0 = smem_to_u32(smem_tc);
    uint32_t smb = (sb0 + 1023u) & ~1023u;

    // lane-invariant fragment addressing precompute
    int a_m  = (lane & 15);            // row offset within m16
    int a_ch = lane >> 4;              // k half
    int b_n  = ((lane >> 4) & 1) * 8 + (lane & 7);
    int b_ch = (lane >> 3) & 1;

    float acc[2][8][4];
#pragma unroll
    for (int i = 0; i < 2; i++)
#pragma unroll
        for (int j = 0; j < 8; j++)
#pragma unroll
            for (int q = 0; q < 4; q++) acc[i][j][q] = 0.f;

    // prologue: stages 0,1
    load_stage(smb,               Ah_g, Al_g, Bh_g, Bl_g, m0, mval, n0, 0,  strideA, tid);
    load_stage(smb + STAGE_BYTES, Ah_g, Al_g, Bh_g, Bl_g, m0, mval, n0, 64, strideA, tid);

    for (int s = 0; s < NS; s++) {
        cp_wait1();
        __syncthreads();
        if (s + 2 < NS) {
            load_stage(smb + ((s + 2) % NSTAGE) * STAGE_BYTES,
                       Ah_g, Al_g, Bh_g, Bl_g, m0, mval, n0, (s + 2) * 64, strideA, tid);
        } else {
            cp_commit();  // keep group count advancing for wait_group 1
        }
        uint32_t stg = smb + (s % NSTAGE) * STAGE_BYTES;
        uint32_t baseAh = stg, baseAl = stg + 16384;
        uint32_t baseBh = stg + 32768, baseBl = stg + 49152;

#pragma unroll
        for (int kk = 0; kk < 4; kk++) {
            uint32_t ah[2][4], al[2][4], bh[16], bl[16];
#pragma unroll
            for (int mt = 0; mt < 2; mt++) {
                int m = wm * 32 + mt * 16 + a_m;
                uint32_t off = sw_off(m, (kk << 1) | a_ch);
                ldsm4(ah[mt], baseAh + off);
                ldsm4(al[mt], baseAl + off);
            }
#pragma unroll
            for (int q = 0; q < 4; q++) {
                int n = wn * 64 + q * 16 + b_n;
                uint32_t off = sw_off(n, (kk << 1) | b_ch);
                ldsm4(&bh[q * 4], baseBh + off);
                ldsm4(&bl[q * 4], baseBl + off);
            }
#pragma unroll
            for (int mt = 0; mt < 2; mt++) {
#pragma unroll
                for (int j = 0; j < 8; j++) {
                    mma16816(acc[mt][j], ah[mt], &bh[j * 2]);
                    mma16816(acc[mt][j], ah[mt], &bl[j * 2]);
                    mma16816(acc[mt][j], al[mt], &bh[j * 2]);
                }
            }
        }
        __syncthreads();
    }

    // ---------------- epilogue ----------------
    float ic = g_c[1];
#pragma unroll
    for (int mt = 0; mt < 2; mt++) {
#pragma unroll
        for (int half = 0; half < 2; half++) {
            int r = m0 + wm * 32 + mt * 16 + (lane >> 2) + half * 8;
            if (r >= NROWS) continue;
            float lam_l = g_lam[r] * ic;
            size_t rb = (size_t)r * NA + n0 + wn * 64 + (lane & 3) * 2;
#pragma unroll
            for (int j = 0; j < 8; j++) {
                size_t gidx = rb + j * 8;
                float v0 = acc[mt][j][half * 2];
                float v1 = acc[mt][j][half * 2 + 1];
                if (MODE != 0) {
                    float2 yy = *(const float2*)(g_y + gidx);
                    v0 = fmaf(yy.x, ic, v0);
                    v1 = fmaf(yy.y, ic, v1);
                }
                float z0 = soft_thresh(v0, lam_l);
                float z1 = soft_thresh(v1, lam_l);
                if (MODE == 0) {
                    *(float2*)(g_y + gidx) = make_float2(v0, v1);
                }
                if (MODE == 2) {
                    *(float2*)(Fout + gidx) = make_float2(z0, z1);
                } else {
                    __nv_bfloat16 h0 = __float2bfloat16(z0);
                    __nv_bfloat16 h1 = __float2bfloat16(z1);
                    float l0 = z0 - __bfloat162float(h0);
                    float l1 = z1 - __bfloat162float(h1);
                    __nv_bfloat162 hp = make_bfloat162(h0, h1);
                    *(uint32_t*)(Zh + gidx) = *(uint32_t*)&hp;
                    *(uint32_t*)(Zl + gidx) = pack_bf16(l0, l1);
                }
            }
        }
    }
}

// ---------------- launch ----------------------------------------------------
extern "C" void kernel_launch(void* const* d_in, const int* in_sizes, int n_in,
                              void* d_out, int out_size) {
    const float* x    = (const float*)d_in[0];
    const float* Dict = (const float*)d_in[1];
    const float* w1   = (const float*)d_in[2];
    const float* b1   = (const float*)d_in[3];
    const float* gg1  = (const float*)d_in[4];
    const float* be1  = (const float*)d_in[5];
    const float* w2   = (const float*)d_in[6];
    const float* b2   = (const float*)d_in[7];
    const float* gg2  = (const float*)d_in[8];
    const float* be2  = (const float*)d_in[9];
    const float* w3   = (const float*)d_in[10];
    const float* b3   = (const float*)d_in[11];
    float* out = (float*)d_out;

    // spectral norm: G = D^T D, G^64 via squarings, power iters, Rayleigh
    kG<<<dim3(16, 16), 256>>>(Dict);
    kSq<<<dim3(16, 16), 256>>>(0, 1.f);
    kSq<<<dim3(16, 16), 256>>>(1, 1.f);
    kSq<<<dim3(16, 16), 256>>>(2, 1.f);
    kSq<<<dim3(16, 16), 256>>>(1, 1.f);
    kSq<<<dim3(16, 16), 256>>>(2, 1.f);
    kSq<<<dim3(16, 16), 256>>>(1, 7.8886090522e-31f);
    kPow<<<1, 512>>>();
    kS2<<<(NA * NA) / 256, 256>>>();

    // operand conversions
    kCvtX<<<2048, 256>>>(x);
    kTrD<<<dim3(32, 16), 256>>>(Dict);

    // MLP -> lam
    size_t mlp_smem = (size_t)128 * 132 * 4 + (size_t)(128 * 64 + 128 * 72) * 4;
    cudaFuncSetAttribute(kMLP, cudaFuncAttributeMaxDynamicSharedMemorySize, (int)mlp_smem);
    int rb = (NROWS + 127) / 128;
    kMLP<<<rb, 256, mlp_smem>>>(x, w1, b1, gg1, be1, w2, b2, gg2, be2, w3, b3);

    // tensor-core GEMM chain (legacy mma.sync path; valid on compute_103)
    const int TC_SMEM = NSTAGE * STAGE_BYTES + 1024;
    cudaFuncSetAttribute(kTC<1024, 0>, cudaFuncAttributeMaxDynamicSharedMemorySize, TC_SMEM);
    cudaFuncSetAttribute(kTC<512, 1>,  cudaFuncAttributeMaxDynamicSharedMemorySize, TC_SMEM);
    cudaFuncSetAttribute(kTC<512, 2>,  cudaFuncAttributeMaxDynamicSharedMemorySize, TC_SMEM);

    dim3 grid(4, rb);
    kTC<1024, 0><<<grid, 256, TC_SMEM>>>(0, nullptr);   // y, z0 -> zA
    kTC<512, 1><<<grid, 256, TC_SMEM>>>(0, nullptr);    // zA -> zB
    kTC<512, 1><<<grid, 256, TC_SMEM>>>(1, nullptr);    // zB -> zA
    kTC<512, 1><<<grid, 256, TC_SMEM>>>(0, nullptr);    // zA -> zB
    kTC<512, 1><<<grid, 256, TC_SMEM>>>(1, nullptr);    // zB -> zA
    kTC<512, 2><<<grid, 256, TC_SMEM>>>(0, out);        // zA -> out (fp32)
}

// round 4
// speedup vs baseline: 2.1072x; 1.2076x over previous
#include <cuda_runtime.h>
#include <cuda_bf16.h>
#include <math.h>
#include <stdint.h>

#define NROWS 50000
#define LDIM  1024
#define NA    512

// ---------------- scratch (device globals; no allocation allowed) ----------
__device__ float g_G[NA * NA];
__device__ float g_H0[NA * NA];
__device__ float g_H1[NA * NA];
__device__ float g_c[2];              // [0]=c, [1]=1/c
__device__ float g_lam[NROWS + 128];
__device__ float g_y[(size_t)NROWS * NA];
__device__ __nv_bfloat16 g_Sh[NA * NA];
__device__ __nv_bfloat16 g_Sl[NA * NA];
__device__ __nv_bfloat16 g_Dth[NA * LDIM];
__device__ __nv_bfloat16 g_Dtl[NA * LDIM];
__device__ __nv_bfloat16 g_w1th[128 * LDIM];
__device__ __nv_bfloat16 g_w1tl[128 * LDIM];
__device__ __nv_bfloat16 g_xh[(size_t)NROWS * LDIM];
__device__ __nv_bfloat16 g_xl[(size_t)NROWS * LDIM];
__device__ __nv_bfloat16 g_zah[(size_t)NROWS * NA];
__device__ __nv_bfloat16 g_zal[(size_t)NROWS * NA];
__device__ __nv_bfloat16 g_zbh[(size_t)NROWS * NA];
__device__ __nv_bfloat16 g_zbl[(size_t)NROWS * NA];

__device__ __forceinline__ float softplus_f(float x) {
    return x > 20.f ? x : log1pf(expf(x));
}
__device__ __forceinline__ float soft_thresh(float v, float l) {
    float a = fabsf(v) - l;
    return a > 0.f ? copysignf(a, v) : 0.f;
}
__device__ __forceinline__ uint32_t pack_bf16(float a, float b) {
    __nv_bfloat162 h = __floats2bfloat162_rn(a, b);
    return *(uint32_t*)&h;
}
__device__ __forceinline__ uint32_t smem_to_u32(const void* smem_ptr) {
    uint32_t addr;
    asm("{ .reg .u64 tmp; cvta.to.shared.u64 tmp, %1; cvt.u32.u64 %0, tmp; }"
        : "=r"(addr) : "l"(smem_ptr));
    return addr;
}
__device__ __forceinline__ void cp16(uint32_t dst, const void* src) {
    asm volatile("cp.async.cg.shared.global [%0], [%1], 16;\n" :: "r"(dst), "l"(src) : "memory");
}
__device__ __forceinline__ void cp_commit() {
    asm volatile("cp.async.commit_group;\n" ::: "memory");
}
__device__ __forceinline__ void cp_wait1() {
    asm volatile("cp.async.wait_group 1;\n" ::: "memory");
}
__device__ __forceinline__ void cp_wait0() {
    asm volatile("cp.async.wait_group 0;\n" ::: "memory");
}
__device__ __forceinline__ void ldsm4(uint32_t* r, uint32_t addr) {
    asm volatile("ldmatrix.sync.aligned.m8n8.x4.shared.b16 {%0,%1,%2,%3}, [%4];\n"
                 : "=r"(r[0]), "=r"(r[1]), "=r"(r[2]), "=r"(r[3]) : "r"(addr));
}
__device__ __forceinline__ void mma16816(float* d, const uint32_t* a, const uint32_t* b) {
    asm volatile(
        "mma.sync.aligned.m16n8k16.row.col.f32.bf16.bf16.f32 "
        "{%0,%1,%2,%3}, {%4,%5,%6,%7}, {%8,%9}, {%0,%1,%2,%3};\n"
        : "+f"(d[0]), "+f"(d[1]), "+f"(d[2]), "+f"(d[3])
        : "r"(a[0]), "r"(a[1]), "r"(a[2]), "r"(a[3]), "r"(b[0]), "r"(b[1]));
}

// ---------------- G = D^T D  (512x512, K=1024) -----------------------------
__global__ void kG(const float* __restrict__ D) {
    __shared__ float Ds1[32][33];
    __shared__ float Ds2[32][33];
    int i0 = blockIdx.x * 32, j0 = blockIdx.y * 32;
    int tid = threadIdx.x;
    int kr = tid >> 3, c4 = (tid & 7) * 4;
    int ty = tid >> 4, tx = tid & 15;
    float acc00 = 0.f, acc01 = 0.f, acc10 = 0.f, acc11 = 0.f;
    for (int k0 = 0; k0 < LDIM; k0 += 32) {
        float4 a = *(const float4*)(D + (size_t)(k0 + kr) * NA + i0 + c4);
        float4 b = *(const float4*)(D + (size_t)(k0 + kr) * NA + j0 + c4);
        Ds1[kr][c4] = a.x; Ds1[kr][c4 + 1] = a.y; Ds1[kr][c4 + 2] = a.z; Ds1[kr][c4 + 3] = a.w;
        Ds2[kr][c4] = b.x; Ds2[kr][c4 + 1] = b.y; Ds2[kr][c4 + 2] = b.z; Ds2[kr][c4 + 3] = b.w;
        __syncthreads();
#pragma unroll
        for (int kk = 0; kk < 32; kk++) {
            float a0 = Ds1[kk][ty * 2], a1 = Ds1[kk][ty * 2 + 1];
            float b0 = Ds2[kk][tx * 2], b1 = Ds2[kk][tx * 2 + 1];
            acc00 = fmaf(a0, b0, acc00); acc01 = fmaf(a0, b1, acc01);
            acc10 = fmaf(a1, b0, acc10); acc11 = fmaf(a1, b1, acc11);
        }
        __syncthreads();
    }
    int i = i0 + ty * 2, j = j0 + tx * 2;
    g_G[i * NA + j] = acc00;       g_G[i * NA + j + 1] = acc01;
    g_G[(i + 1) * NA + j] = acc10; g_G[(i + 1) * NA + j + 1] = acc11;
}

// ---------------- H_out = alpha * H_in * H_in; tile 64(M)x32(N), 4x2/thr ----
__global__ void kSq(int sel, float alpha) {
    const float* Hin = (sel == 0) ? g_G : (sel == 1) ? g_H0 : g_H1;
    float* Hout = (sel == 1) ? g_H1 : g_H0;
    __shared__ float As[32][64];   // [k][i]
    __shared__ float Bs[32][32];   // [k][j]
    int n0 = blockIdx.x * 32, m0 = blockIdx.y * 64;
    int tid = threadIdx.x;
    int ty = tid >> 4, tx = tid & 15;   // ty 0..15 (4 rows each), tx 0..15 (2 cols each)
    float acc[4][2];
#pragma unroll
    for (int i = 0; i < 4; i++) { acc[i][0] = 0.f; acc[i][1] = 0.f; }
    for (int k0 = 0; k0 < NA; k0 += 32) {
        // A: 64 rows x 32 k -> transposed into As[k][i]
#pragma unroll
        for (int t = 0; t < 2; t++) {
            int idx = tid + t * 256;        // 0..511
            int r = idx >> 3, c4 = (idx & 7) * 4;
            float4 a = *(const float4*)(Hin + (size_t)(m0 + r) * NA + k0 + c4);
            As[c4 + 0][r] = a.x; As[c4 + 1][r] = a.y;
            As[c4 + 2][r] = a.z; As[c4 + 3][r] = a.w;
        }
        // B: 32 k-rows x 32 cols direct
        {
            int r = tid >> 3, c4 = (tid & 7) * 4;
            *(float4*)(&Bs[r][c4]) = *(const float4*)(Hin + (size_t)(k0 + r) * NA + n0 + c4);
        }
        __syncthreads();
#pragma unroll
        for (int kk = 0; kk < 32; kk++) {
            float4 a4 = *(float4*)(&As[kk][ty * 4]);
            float b0 = Bs[kk][tx * 2], b1 = Bs[kk][tx * 2 + 1];
            acc[0][0] = fmaf(a4.x, b0, acc[0][0]); acc[0][1] = fmaf(a4.x, b1, acc[0][1]);
            acc[1][0] = fmaf(a4.y, b0, acc[1][0]); acc[1][1] = fmaf(a4.y, b1, acc[1][1]);
            acc[2][0] = fmaf(a4.z, b0, acc[2][0]); acc[2][1] = fmaf(a4.z, b1, acc[2][1]);
            acc[3][0] = fmaf(a4.w, b0, acc[3][0]); acc[3][1] = fmaf(a4.w, b1, acc[3][1]);
        }
        __syncthreads();
    }
#pragma unroll
    for (int i = 0; i < 4; i++) {
        int r = m0 + ty * 4 + i, cc = n0 + tx * 2;
        Hout[r * NA + cc] = alpha * acc[i][0];
        Hout[r * NA + cc + 1] = alpha * acc[i][1];
    }
}

// ---------------- power iteration on H1 (= scaled G^64) + Rayleigh on G ----
__global__ void kPow() {
    __shared__ float v[NA];
    __shared__ float red[NA];
    int t = threadIdx.x;  // 512 threads
    v[t] = 1.f;
    __syncthreads();
    for (int it = 0; it < 24; it++) {
        float s = 0.f;
        const float4* row = (const float4*)(g_H1 + (size_t)t * NA);
#pragma unroll 4
        for (int k = 0; k < NA / 4; k++) {
            float4 h = row[k];
            s = fmaf(h.x, v[4 * k], s);
            s = fmaf(h.y, v[4 * k + 1], s);
            s = fmaf(h.z, v[4 * k + 2], s);
            s = fmaf(h.w, v[4 * k + 3], s);
        }
        red[t] = s * s;
        __syncthreads();
        for (int off = 256; off > 0; off >>= 1) {
            if (t < off) red[t] += red[t + off];
            __syncthreads();
        }
        float inv = rsqrtf(red[0]);
        __syncthreads();
        v[t] = s * inv;
        __syncthreads();
    }
    float u = 0.f;
    const float4* grow = (const float4*)(g_G + (size_t)t * NA);
#pragma unroll 4
    for (int k = 0; k < NA / 4; k++) {
        float4 h = grow[k];
        u = fmaf(h.x, v[4 * k], u);
        u = fmaf(h.y, v[4 * k + 1], u);
        u = fmaf(h.z, v[4 * k + 2], u);
        u = fmaf(h.w, v[4 * k + 3], u);
    }
    float vt = v[t];
    red[t] = u * vt;
    __syncthreads();
    for (int off = 256; off > 0; off >>= 1) {
        if (t < off) red[t] += red[t + off];
        __syncthreads();
    }
    float num = red[0];
    __syncthreads();
    red[t] = vt * vt;
    __syncthreads();
    for (int off = 256; off > 0; off >>= 1) {
        if (t < off) red[t] += red[t + off];
        __syncthreads();
    }
    if (t == 0) {
        float c = num / red[0];
        g_c[0] = c;
        g_c[1] = 1.f / c;
    }
}

// ---------------- Sh/Sl = split_bf16(I - G/c)  (S symmetric) ---------------
__global__ void kS2() {
    int idx = blockIdx.x * 256 + threadIdx.x;
    float ic = g_c[1];
    int i = idx >> 9, j = idx & (NA - 1);
    float val = -g_G[idx] * ic;
    if (i == j) val += 1.f;
    __nv_bfloat16 h = __float2bfloat16(val);
    g_Sh[idx] = h;
    g_Sl[idx] = __float2bfloat16(val - __bfloat162float(h));
}

// ---------------- x -> xh/xl bf16 split --------------------------------------
__global__ void kCvtX(const float* __restrict__ x) {
    const int NV = NROWS * LDIM / 4;
    uint32_t* xh = (uint32_t*)g_xh;
    uint32_t* xl = (uint32_t*)g_xl;
    for (int v = blockIdx.x * blockDim.x + threadIdx.x; v < NV; v += gridDim.x * blockDim.x) {
        float4 a = *(const float4*)(x + (size_t)v * 4);
        __nv_bfloat16 h0 = __float2bfloat16(a.x), h1 = __float2bfloat16(a.y);
        __nv_bfloat16 h2 = __float2bfloat16(a.z), h3 = __float2bfloat16(a.w);
        float l0 = a.x - __bfloat162float(h0), l1 = a.y - __bfloat162float(h1);
        float l2 = a.z - __bfloat162float(h2), l3 = a.w - __bfloat162float(h3);
        __nv_bfloat162 hh0 = make_bfloat162(h0, h1);
        __nv_bfloat162 hh1 = make_bfloat162(h2, h3);
        xh[v * 2] = *(uint32_t*)&hh0;
        xh[v * 2 + 1] = *(uint32_t*)&hh1;
        xl[v * 2] = pack_bf16(l0, l1);
        xl[v * 2 + 1] = pack_bf16(l2, l3);
    }
}

// ---------------- Dict transpose + split: Dt[n][k] = D[k][n] -----------------
__global__ void kTrD(const float* __restrict__ D) {
    __shared__ float t[32][33];
    int k0 = blockIdx.x * 32, n0 = blockIdx.y * 32;
    int tx = threadIdx.x & 31, ty = threadIdx.x >> 5;
    for (int i = ty; i < 32; i += 8) t[i][tx] = D[(size_t)(k0 + i) * NA + n0 + tx];
    __syncthreads();
    for (int i = ty; i < 32; i += 8) {
        float val = t[tx][i];
        size_t o = (size_t)(n0 + i) * LDIM + k0 + tx;
        __nv_bfloat16 h = __float2bfloat16(val);
        g_Dth[o] = h;
        g_Dtl[o] = __float2bfloat16(val - __bfloat162float(h));
    }
}

// ---------------- w1 transpose + split: w1t[n][k] = w1[k][n] ----------------
__global__ void kTrW1(const float* __restrict__ W) {
    __shared__ float t[32][33];
    int k0 = blockIdx.x * 32, n0 = blockIdx.y * 32;
    int tx = threadIdx.x & 31, ty = threadIdx.x >> 5;
    for (int i = ty; i < 32; i += 8) t[i][tx] = W[(size_t)(k0 + i) * 128 + n0 + tx];
    __syncthreads();
    for (int i = ty; i < 32; i += 8) {
        float val = t[tx][i];
        size_t o = (size_t)(n0 + i) * LDIM + k0 + tx;
        __nv_bfloat16 h = __float2bfloat16(val);
        g_w1th[o] = h;
        g_w1tl[o] = __float2bfloat16(val - __bfloat162float(h));
    }
}

// ================= mma.sync split-bf16 GEMM =================================
// CTA 128(M) x NT(N), 512 threads / 16 warps (4M x 4N), warp tile 32 x NT/4.
// K staged at 64 bf16, SW128 XOR swizzle, 2-stage cp.async double buffer.
// Stage layout: Ah 0 | Al 16K | Bh 32K | Bl 32K+NT*128.  SS = 32K + NT*256.
// Products per k16: (Ah,Bh), (Ah,Bl), (Al,Bh).
// MODE 0: y = x@Dict (KT=1024, NT=256): write y fp32 + z0 split
// MODE 1: z' = st(z@S + y/c) (KT=512, NT=256): write z' split
// MODE 2: same as 1 but write fp32 to Fout
// MODE 3: h1 = x@w1t (KT=1024, NT=128) + full fused MLP tail -> g_lam

__device__ __forceinline__ uint32_t sw_off(int row, int c) {
    return (uint32_t)(((row >> 3) << 10) | ((row & 7) << 7) | ((c ^ (row & 7)) << 4));
}

template <int NT>
__device__ __forceinline__ void load_stage(uint32_t smbase,
                                           const __nv_bfloat16* Ah, const __nv_bfloat16* Al,
                                           const __nv_bfloat16* Bh, const __nv_bfloat16* Bl,
                                           int m0, int mval, int n0, int k0,
                                           int stride, int tid) {
#pragma unroll
    for (int t = 0; t < 2; t++) {
        int idx = tid + t * 512;       // 0..1023 over 128 rows x 8 chunks
        int row = idx >> 3, c = idx & 7;
        uint32_t so = sw_off(row, c);
        int ar = m0 + (row < mval ? row : mval - 1);
        cp16(smbase + so,         Ah + (size_t)ar * stride + k0 + c * 8);
        cp16(smbase + 16384 + so, Al + (size_t)ar * stride + k0 + c * 8);
    }
#pragma unroll
    for (int t = 0; t < NT / 64; t++) {
        int idx = tid + t * 512;       // over NT rows x 8 chunks
        int row = idx >> 3, c = idx & 7;
        uint32_t so = sw_off(row, c);
        int br = n0 + row;
        cp16(smbase + 32768 + so,            Bh + (size_t)br * stride + k0 + c * 8);
        cp16(smbase + 32768 + NT * 128 + so, Bl + (size_t)br * stride + k0 + c * 8);
    }
    cp_commit();
}

extern __shared__ char smem_tc[];

template <int KT, int NT, int MODE>
__global__ void __launch_bounds__(512, 1) kTC(int dir, float* __restrict__ Fout,
                                              const float* __restrict__ p1,
                                              const float* __restrict__ p2,
                                              const float* __restrict__ p3,
                                              const float* __restrict__ p4,
                                              const float* __restrict__ p5,
                                              const float* __restrict__ p6,
                                              const float* __restrict__ p7,
                                              const float* __restrict__ p8,
                                              const float* __restrict__ p9) {
    const int NS = KT / 64;
    const int SS = 32768 + NT * 256;
    const int WN = NT / 4;            // warp n-width: 64 or 32
    const int NQ = WN / 16;           // 4 or 2
    const int NJ = WN / 8;            // 8 or 4
    int tid = threadIdx.x;
    int wid = tid >> 5, lane = tid & 31;
    int wm = wid & 3, wn = wid >> 2;
    int m0 = blockIdx.y * 128;
    int n0 = blockIdx.x * NT;
    int mval = NROWS - m0; if (mval > 128) mval = 128;

    const __nv_bfloat16 *Ah_g, *Al_g, *Bh_g, *Bl_g;
    __nv_bfloat16 *Zh = nullptr, *Zl = nullptr;
    if (MODE == 0) {
        Ah_g = g_xh; Al_g = g_xl; Bh_g = g_Dth; Bl_g = g_Dtl;
        Zh = g_zah; Zl = g_zal;
    } else if (MODE == 3) {
        Ah_g = g_xh; Al_g = g_xl; Bh_g = g_w1th; Bl_g = g_w1tl;
    } else {
        Ah_g = dir ? g_zbh : g_zah; Al_g = dir ? g_zbl : g_zal;
        Bh_g = g_Sh; Bl_g = g_Sl;
        Zh = dir ? g_zah : g_zbh;  Zl = dir ? g_zal : g_zbl;
    }

    uint32_t sb0 = smem_to_u32(smem_tc);
    uint32_t smb = (sb0 + 1023u) & ~1023u;
    char* smc = smem_tc + (smb - sb0);

    int a_m  = (lane & 15);
    int a_ch = lane >> 4;
    int b_n  = ((lane >> 4) & 1) * 8 + (lane & 7);
    int b_ch = (lane >> 3) & 1;

    float acc[2][NJ][4];
#pragma unroll
    for (int i = 0; i < 2; i++)
#pragma unroll
        for (int j = 0; j < NJ; j++)
#pragma unroll
            for (int q = 0; q < 4; q++) acc[i][j][q] = 0.f;

    load_stage<NT>(smb,      Ah_g, Al_g, Bh_g, Bl_g, m0, mval, n0, 0,  KT, tid);
    load_stage<NT>(smb + SS, Ah_g, Al_g, Bh_g, Bl_g, m0, mval, n0, 64, KT, tid);

    for (int s = 0; s < NS; s++) {
        cp_wait1();
        __syncthreads();
        uint32_t stg = smb + (s & 1) * SS;
        uint32_t bAh = stg, bAl = stg + 16384;
        uint32_t bBh = stg + 32768, bBl = stg + 32768 + NT * 128;
#pragma unroll
        for (int kk = 0; kk < 4; kk++) {
            uint32_t ah[2][4], al[2][4];
#pragma unroll
            for (int mt = 0; mt < 2; mt++) {
                uint32_t off = sw_off(wm * 32 + mt * 16 + a_m, (kk << 1) | a_ch);
                ldsm4(ah[mt], bAh + off);
                ldsm4(al[mt], bAl + off);
            }
#pragma unroll
            for (int q = 0; q < NQ; q++) {
                uint32_t bh4[4], bl4[4];
                uint32_t off = sw_off(wn * WN + q * 16 + b_n, (kk << 1) | b_ch);
                ldsm4(bh4, bBh + off);
                ldsm4(bl4, bBl + off);
#pragma unroll
                for (int mt = 0; mt < 2; mt++) {
#pragma unroll
                    for (int jj = 0; jj < 2; jj++) {
                        mma16816(acc[mt][q * 2 + jj], ah[mt], &bh4[jj * 2]);
                        mma16816(acc[mt][q * 2 + jj], ah[mt], &bl4[jj * 2]);
                        mma16816(acc[mt][q * 2 + jj], al[mt], &bh4[jj * 2]);
                    }
                }
            }
        }
        __syncthreads();
        if (s + 2 < NS) {
            load_stage<NT>(smb + (s & 1) * SS, Ah_g, Al_g, Bh_g, Bl_g,
                           m0, mval, n0, (s + 2) * 64, KT, tid);
        } else {
            cp_commit();
        }
    }

    if (MODE != 3) {
        // ---------------- GEMM epilogue ----------------
        float ic = g_c[1];
#pragma unroll
        for (int mt = 0; mt < 2; mt++) {
#pragma unroll
            for (int half = 0; half < 2; half++) {
                int r = m0 + wm * 32 + mt * 16 + (lane >> 2) + half * 8;
                if (r >= NROWS) continue;
                float lam_l = g_lam[r] * ic;
                size_t rb = (size_t)r * NA + n0 + wn * WN + (lane & 3) * 2;
#pragma unroll
                for (int j = 0; j < NJ; j++) {
                    size_t gidx = rb + j * 8;
                    float v0 = acc[mt][j][half * 2];
                    float v1 = acc[mt][j][half * 2 + 1];
                    if (MODE != 0) {
                        float2 yy = *(const float2*)(g_y + gidx);
                        v0 = fmaf(yy.x, ic, v0);
                        v1 = fmaf(yy.y, ic, v1);
                    }
                    float z0 = soft_thresh(v0, lam_l);
                    float z1 = soft_thresh(v1, lam_l);
                    if (MODE == 0) {
                        *(float2*)(g_y + gidx) = make_float2(v0, v1);
                    }
                    if (MODE == 2) {
                        *(float2*)(Fout + gidx) = make_float2(z0, z1);
                    } else {
                        __nv_bfloat16 h0 = __float2bfloat16(z0);
                        __nv_bfloat16 h1 = __float2bfloat16(z1);
                        float l0 = z0 - __bfloat162float(h0);
                        float l1 = z1 - __bfloat162float(h1);
                        __nv_bfloat162 hp = make_bfloat162(h0, h1);
                        *(uint32_t*)(Zh + gidx) = *(uint32_t*)&hp;
                        *(uint32_t*)(Zl + gidx) = pack_bf16(l0, l1);
                    }
                }
            }
        }
    } else {
        // ---------------- fused MLP tail (NT=128): LN1+sp, w2, LN2+sp, w3 ---
        const float* b1  = p1; const float* gg1 = p2; const float* be1 = p3;
        const float* w2  = p4; const float* b2  = p5; const float* gg2 = p6;
        const float* be2 = p7; const float* w3  = p8; const float* b3  = p9;
        const int LDH = 132;
        float* hbuf = (float*)(smc + 2 * SS);
        // accumulators -> hbuf (+bias)
#pragma unroll
        for (int mt = 0; mt < 2; mt++) {
#pragma unroll
            for (int half = 0; half < 2; half++) {
                int rl = wm * 32 + mt * 16 + (lane >> 2) + half * 8;
#pragma unroll
                for (int j = 0; j < NJ; j++) {
                    int cc = wn * WN + j * 8 + (lane & 3) * 2;
                    hbuf[rl * LDH + cc]     = acc[mt][j][half * 2] + b1[cc];
                    hbuf[rl * LDH + cc + 1] = acc[mt][j][half * 2 + 1] + b1[cc + 1];
                }
            }
        }
        cp_wait0();
        __syncthreads();
        int warp = wid;
        // LN1 + softplus (rows 0..127, 16 warps)
        for (int r = warp; r < 128; r += 16) {
            float vals[4];
            float s = 0.f, s2 = 0.f;
#pragma unroll
            for (int i = 0; i < 4; i++) {
                float h = hbuf[r * LDH + lane * 4 + i];
                vals[i] = h; s += h; s2 += h * h;
            }
#pragma unroll
            for (int off = 16; off; off >>= 1) {
                s += __shfl_xor_sync(0xffffffffu, s, off);
                s2 += __shfl_xor_sync(0xffffffffu, s2, off);
            }
            float mu = s * (1.f / 128.f);
            float var = s2 * (1.f / 128.f) - mu * mu;
            float inv = rsqrtf(var + 1e-5f);
#pragma unroll
            for (int i = 0; i < 4; i++) {
                int cc = lane * 4 + i;
                float t2 = (vals[i] - mu) * inv * gg1[cc] + be1[cc];
                hbuf[r * LDH + cc] = softplus_f(t2);
            }
        }
        // w2 into smem (overlay stage region)
        float* ws2 = (float*)smc;            // [128][64] 32KB
        float* h2 = (float*)(smc + 32768);   // [128][72] 36.8KB
        const int LDH2 = 72;
#pragma unroll
        for (int t = 0; t < 4; t++) {
            int idx = tid + t * 512;
            *(float4*)(ws2 + idx * 4) = *(const float4*)(w2 + (size_t)idx * 4);
        }
        __syncthreads();
        // h2 = hbuf @ w2 + b2 : each thread 2 rows x 8 cols
        {
            int r0 = (tid >> 3) * 2, c0 = (tid & 7) * 8;
            float a2[2][8];
#pragma unroll
            for (int i = 0; i < 2; i++)
#pragma unroll
                for (int j = 0; j < 8; j++) a2[i][j] = 0.f;
            for (int k = 0; k < 128; k++) {
                float av0 = hbuf[(r0 + 0) * LDH + k];
                float av1 = hbuf[(r0 + 1) * LDH + k];
                float bv[8];
#pragma unroll
                for (int j = 0; j < 8; j++) bv[j] = ws2[k * 64 + c0 + j];
#pragma unroll
                for (int j = 0; j < 8; j++) {
                    a2[0][j] = fmaf(av0, bv[j], a2[0][j]);
                    a2[1][j] = fmaf(av1, bv[j], a2[1][j]);
                }
            }
#pragma unroll
            for (int i = 0; i < 2; i++)
#pragma unroll
                for (int j = 0; j < 8; j++)
                    h2[(r0 + i) * LDH2 + c0 + j] = a2[i][j] + b2[c0 + j];
        }
        __syncthreads();
        // LN2 + softplus over 64
        for (int r = warp; r < 128; r += 16) {
            float vals[2];
            float s = 0.f, s2 = 0.f;
#pragma unroll
            for (int i = 0; i < 2; i++) {
                float h = h2[r * LDH2 + lane * 2 + i];
                vals[i] = h; s += h; s2 += h * h;
            }
#pragma unroll
            for (int off = 16; off; off >>= 1) {
                s += __shfl_xor_sync(0xffffffffu, s, off);
                s2 += __shfl_xor_sync(0xffffffffu, s2, off);
            }
            float mu = s * (1.f / 64.f);
            float var = s2 * (1.f / 64.f) - mu * mu;
            float inv = rsqrtf(var + 1e-5f);
#pragma unroll
            for (int i = 0; i < 2; i++) {
                int cc = lane * 2 + i;
                float t2 = (vals[i] - mu) * inv * gg2[cc] + be2[cc];
                h2[r * LDH2 + cc] = softplus_f(t2);
            }
        }
        __syncthreads();
        if (tid < 128) {
            int r = tid;
            float s = 0.f;
            for (int k = 0; k < 64; k++) s = fmaf(h2[r * LDH2 + k], w3[k], s);
            if (m0 + r < NROWS) g_lam[m0 + r] = s + b3[0];
        }
    }
}

// ---------------- launch ----------------------------------------------------
extern "C" void kernel_launch(void* const* d_in, const int* in_sizes, int n_in,
                              void* d_out, int out_size) {
    const float* x    = (const float*)d_in[0];
    const float* Dict = (const float*)d_in[1];
    const float* w1   = (const float*)d_in[2];
    const float* b1   = (const float*)d_in[3];
    const float* gg1  = (const float*)d_in[4];
    const float* be1  = (const float*)d_in[5];
    const float* w2   = (const float*)d_in[6];
    const float* b2   = (const float*)d_in[7];
    const float* gg2  = (const float*)d_in[8];
    const float* be2  = (const float*)d_in[9];
    const float* w3   = (const float*)d_in[10];
    const float* b3   = (const float*)d_in[11];
    float* out = (float*)d_out;

    // spectral norm: G = D^T D, G^64 via squarings, power iters, Rayleigh
    kG<<<dim3(16, 16), 256>>>(Dict);
    kSq<<<dim3(16, 8), 256>>>(0, 1.f);
    kSq<<<dim3(16, 8), 256>>>(1, 1.f);
    kSq<<<dim3(16, 8), 256>>>(2, 1.f);
    kSq<<<dim3(16, 8), 256>>>(1, 1.f);
    kSq<<<dim3(16, 8), 256>>>(2, 1.f);
    kSq<<<dim3(16, 8), 256>>>(1, 7.8886090522e-31f);
    kPow<<<1, 512>>>();
    kS2<<<(NA * NA) / 256, 256>>>();

    // operand conversions
    kCvtX<<<2048, 256>>>(x);
    kTrD<<<dim3(32, 16), 256>>>(Dict);
    kTrW1<<<dim3(32, 4), 256>>>(w1);

    int rb = (NROWS + 127) / 128;

    // smem sizes
    const int SS256 = 32768 + 256 * 256;           // 98304
    const int SS128 = 32768 + 128 * 256;           // 65536
    const int SM_G = 2 * SS256 + 1024;             // 197632
    const int SM_M = 2 * SS128 + 128 * 132 * 4 + 1024;  // 199680
    cudaFuncSetAttribute(kTC<1024, 128, 3>, cudaFuncAttributeMaxDynamicSharedMemorySize, SM_M);
    cudaFuncSetAttribute(kTC<1024, 256, 0>, cudaFuncAttributeMaxDynamicSharedMemorySize, SM_G);
    cudaFuncSetAttribute(kTC<512, 256, 1>,  cudaFuncAttributeMaxDynamicSharedMemorySize, SM_G);
    cudaFuncSetAttribute(kTC<512, 256, 2>,  cudaFuncAttributeMaxDynamicSharedMemorySize, SM_G);

    // MLP -> lam (tensor-core layer 1 + fused tail)
    kTC<1024, 128, 3><<<dim3(1, rb), 512, SM_M>>>(0, nullptr,
        b1, gg1, be1, w2, b2, gg2, be2, w3, b3);

    // GEMM chain
    dim3 grid(2, rb);
    kTC<1024, 256, 0><<<grid, 512, SM_G>>>(0, nullptr, 0,0,0,0,0,0,0,0,0);  // y, z0 -> zA
    kTC<512, 256, 1><<<grid, 512, SM_G>>>(0, nullptr, 0,0,0,0,0,0,0,0,0);   // zA -> zB
    kTC<512, 256, 1><<<grid, 512, SM_G>>>(1, nullptr, 0,0,0,0,0,0,0,0,0);   // zB -> zA
    kTC<512, 256, 1><<<grid, 512, SM_G>>>(0, nullptr, 0,0,0,0,0,0,0,0,0);   // zA -> zB
    kTC<512, 256, 1><<<grid, 512, SM_G>>>(1, nullptr, 0,0,0,0,0,0,0,0,0);   // zB -> zA
    kTC<512, 256, 2><<<grid, 512, SM_G>>>(0, out, 0,0,0,0,0,0,0,0,0);       // zA -> out
}